// round 1
// baseline (speedup 1.0000x reference)
#include <cuda_runtime.h>
#include <cuda_bf16.h>
#include <cstdint>

// CapsuleRoutingPooling, B=16 C=64 H=64 W=64 D=16, k=2, routing_iteration=3.
//
// Key insight: the reference computes c = softmax(b, axis=3) where axis 3 has
// length 1 -> c == 1.0 always. The entire dynamic-routing loop is a no-op and
// the op reduces to a 2x2 vector sum-pool followed by squash():
//   s = sum over the 2x2 window of the D=16 input vectors
//   out = (|s|^2 / (1+|s|^2)) * s / (|s| + 1e-8)
//
// Pure streaming kernel: 256 MiB read + 64 MiB write, HBM-bound.

static constexpr int B  = 16;
static constexpr int C  = 64;
static constexpr int H  = 64;
static constexpr int W  = 64;
static constexpr int D  = 16;
static constexpr int NH = H / 2;          // 32
static constexpr int NW = W / 2;          // 32
static constexpr int NVEC = B * C * NH * NW;   // 1,048,576 output vectors

__global__ __launch_bounds__(256) void capsule_pool_squash_kernel(
    const float* __restrict__ in, float* __restrict__ out)
{
    const int vec = blockIdx.x * blockDim.x + threadIdx.x;
    if (vec >= NVEC) return;

    const int nw = vec & (NW - 1);
    const int nh = (vec >> 5) & (NH - 1);
    const int bc = vec >> 10;                       // b*C + c, 0..1023

    // Input row0: (bc, 2*nh, 2*nw, 0); 32 contiguous floats cover dx=0 and dx=1.
    // Row1 is one W-row further: +W*D = +1024 floats.
    const size_t base = ((size_t)bc * H + 2 * nh) * (size_t)(W * D)
                      + (size_t)nw * (2 * D);
    const float4* __restrict__ r0 = reinterpret_cast<const float4*>(in + base);
    const float4* __restrict__ r1 = r0 + (W * D) / 4;   // +256 float4

    // 16 independent 16B loads, front-batched for MLP.
    float4 a0 = __ldcs(r0 + 0), a1 = __ldcs(r0 + 1), a2 = __ldcs(r0 + 2), a3 = __ldcs(r0 + 3);
    float4 b0 = __ldcs(r0 + 4), b1 = __ldcs(r0 + 5), b2 = __ldcs(r0 + 6), b3 = __ldcs(r0 + 7);
    float4 c0 = __ldcs(r1 + 0), c1 = __ldcs(r1 + 1), c2 = __ldcs(r1 + 2), c3 = __ldcs(r1 + 3);
    float4 d0 = __ldcs(r1 + 4), d1 = __ldcs(r1 + 5), d2 = __ldcs(r1 + 6), d3 = __ldcs(r1 + 7);

    float4 s0, s1, s2, s3;
    s0.x = (a0.x + b0.x) + (c0.x + d0.x);
    s0.y = (a0.y + b0.y) + (c0.y + d0.y);
    s0.z = (a0.z + b0.z) + (c0.z + d0.z);
    s0.w = (a0.w + b0.w) + (c0.w + d0.w);
    s1.x = (a1.x + b1.x) + (c1.x + d1.x);
    s1.y = (a1.y + b1.y) + (c1.y + d1.y);
    s1.z = (a1.z + b1.z) + (c1.z + d1.z);
    s1.w = (a1.w + b1.w) + (c1.w + d1.w);
    s2.x = (a2.x + b2.x) + (c2.x + d2.x);
    s2.y = (a2.y + b2.y) + (c2.y + d2.y);
    s2.z = (a2.z + b2.z) + (c2.z + d2.z);
    s2.w = (a2.w + b2.w) + (c2.w + d2.w);
    s3.x = (a3.x + b3.x) + (c3.x + d3.x);
    s3.y = (a3.y + b3.y) + (c3.y + d3.y);
    s3.z = (a3.z + b3.z) + (c3.z + d3.z);
    s3.w = (a3.w + b3.w) + (c3.w + d3.w);

    float sq = s0.x*s0.x + s0.y*s0.y + s0.z*s0.z + s0.w*s0.w
             + s1.x*s1.x + s1.y*s1.y + s1.z*s1.z + s1.w*s1.w
             + s2.x*s2.x + s2.y*s2.y + s2.z*s2.z + s2.w*s2.w
             + s3.x*s3.x + s3.y*s3.y + s3.z*s3.z + s3.w*s3.w;

    // squash scale: sq/(1+sq) * 1/(sqrt(sq)+1e-8)
    const float scale = sq / ((1.0f + sq) * (sqrtf(sq) + 1e-8f));

    s0.x *= scale; s0.y *= scale; s0.z *= scale; s0.w *= scale;
    s1.x *= scale; s1.y *= scale; s1.z *= scale; s1.w *= scale;
    s2.x *= scale; s2.y *= scale; s2.z *= scale; s2.w *= scale;
    s3.x *= scale; s3.y *= scale; s3.z *= scale; s3.w *= scale;

    float4* __restrict__ o = reinterpret_cast<float4*>(out + (size_t)vec * D);
    __stcs(o + 0, s0);
    __stcs(o + 1, s1);
    __stcs(o + 2, s2);
    __stcs(o + 3, s3);
}

extern "C" void kernel_launch(void* const* d_in, const int* in_sizes, int n_in,
                              void* d_out, int out_size)
{
    const float* in = (const float*)d_in[0];
    float* out = (float*)d_out;
    const int threads = 256;
    const int blocks = NVEC / threads;   // 4096, exact
    capsule_pool_squash_kernel<<<blocks, threads>>>(in, out);
}

// round 3
// speedup vs baseline: 1.7051x; 1.7051x over previous
#include <cuda_runtime.h>
#include <cuda_bf16.h>
#include <cstdint>

// CapsuleRoutingPooling, B=16 C=64 H=64 W=64 D=16, k=2.
// softmax over a length-1 axis => c==1 => routing loop is a no-op.
// out = squash( 2x2 sum-pool of D=16 vectors ).
//
// R2 (resubmit; R2 bench died to container-level infra failure, kernel
// re-audited for OOB/capture issues — none found).
//
// R1 kernel was L1-wavefront-bound (each LDG.128 touched 32 distinct 128B
// lines -> L1 79.9%, DRAM only 43.9%). This version stages through shared
// memory with fully coalesced global loads/stores:
//   block b owns (bc, nh_pair): input = 1024 contiguous float4 (16KB),
//   output = 256 contiguous float4 (4KB). Pool+squash computed from smem
//   with a swizzle to avoid the 2-way LDS bank conflict, |s|^2 via
//   shfl_xor across the 4-lane dq group.

static constexpr int NBLOCKS = 16 * 64 * 16;   // B*C * (NH/2) = 16384

__device__ __forceinline__ int swz(int idx) {
    // XOR bit2 of the float4 index with bit3: nw-adjacent float4 groups land
    // in different bank octants for the LDS.128 read pattern, while
    // consecutive-index STS stays conflict-free. Involution, stays in-range.
    return idx ^ ((idx >> 1) & 4);
}

__global__ __launch_bounds__(256) void capsule_pool_squash_kernel(
    const float4* __restrict__ in, float4* __restrict__ out)
{
    __shared__ float4 sm[1024];   // 16KB: 4 input rows x 256 float4

    const int t = threadIdx.x;
    const size_t ibase = (size_t)blockIdx.x * 1024;

    // ---- coalesced load: 4 x LDG.128 per thread, consecutive lanes ----
    float4 l0 = __ldcs(in + ibase + t);
    float4 l1 = __ldcs(in + ibase + t + 256);
    float4 l2 = __ldcs(in + ibase + t + 512);
    float4 l3 = __ldcs(in + ibase + t + 768);
    sm[swz(t)]       = l0;
    sm[swz(t + 256)] = l1;
    sm[swz(t + 512)] = l2;
    sm[swz(t + 768)] = l3;
    __syncthreads();

    // ---- compute: thread t owns output float4 (nh_loc, nw, dq) ----
    const int nh_loc = t >> 7;        // 0..1
    const int rem    = t & 127;
    const int nw     = rem >> 2;      // 0..31
    const int dq     = rem & 3;       // 0..3  (float4 index within D=16)

    const int r = nh_loc * 512 + nw * 8 + dq;
    const float4 a = sm[swz(r)];          // row 2*nh_loc,   dx=0
    const float4 b = sm[swz(r + 4)];      // row 2*nh_loc,   dx=1
    const float4 c = sm[swz(r + 256)];    // row 2*nh_loc+1, dx=0
    const float4 d = sm[swz(r + 260)];    // row 2*nh_loc+1, dx=1

    float4 s;
    s.x = (a.x + b.x) + (c.x + d.x);
    s.y = (a.y + b.y) + (c.y + d.y);
    s.z = (a.z + b.z) + (c.z + d.z);
    s.w = (a.w + b.w) + (c.w + d.w);

    // |s|^2 over the full 16-dim vector: butterfly across the 4-lane dq group.
    float sq = s.x * s.x + s.y * s.y + s.z * s.z + s.w * s.w;
    sq += __shfl_xor_sync(0xffffffffu, sq, 1);
    sq += __shfl_xor_sync(0xffffffffu, sq, 2);

    // squash scale: sq/(1+sq) * 1/(sqrt(sq)+1e-8)
    const float scale = sq / ((1.0f + sq) * (sqrtf(sq) + 1e-8f));
    s.x *= scale; s.y *= scale; s.z *= scale; s.w *= scale;

    // ---- coalesced store: consecutive lanes -> consecutive float4 ----
    __stcs(out + (size_t)blockIdx.x * 256 + t, s);
}

extern "C" void kernel_launch(void* const* d_in, const int* in_sizes, int n_in,
                              void* d_out, int out_size)
{
    const float4* in  = (const float4*)d_in[0];
    float4* out = (float4*)d_out;
    capsule_pool_squash_kernel<<<NBLOCKS, 256>>>(in, out);
}